// round 15
// baseline (speedup 1.0000x reference)
#include <cuda_runtime.h>
#include <cstddef>

static constexpr int T_  = 32;
static constexpr int B_  = 512;
static constexpr int NS_ = 64;
static constexpr int NC_ = 32;
static constexpr int SZ_ = 96;   // NS + NC

using ull = unsigned long long;

// ---------------- scratch (static device globals; no allocation) ----------------
__device__ float g_costpart[T_ * B_];                 // per (t,b) old-cost contribution
__device__ float g_q0[T_ * B_];
__device__ float g_q1[T_ * B_];
__device__ float g_q2[T_ * B_];
__device__ float g_K[(size_t)T_ * B_ * NC_ * NS_];    // gains
__device__ float g_kv[(size_t)T_ * B_ * NC_];
__device__ float g_z0[(size_t)T_ * B_ * SZ_];         // base rollout [nx;nu] (alpha=0)
__device__ float g_dz[(size_t)T_ * B_ * SZ_];         // d/dalpha of rollout
__device__ float g_alpha[B_];

// ---------------- packed f32x2 helpers ----------------
__device__ __forceinline__ void fma2(ull& acc, ull x, ull b) {
    asm("fma.rn.f32x2 %0, %1, %2, %0;" : "+l"(acc) : "l"(x), "l"(b));
}
__device__ __forceinline__ ull pack2(float lo, float hi) {
    ull r;
    asm("mov.b64 %0, {%1, %2};" : "=l"(r) : "f"(lo), "f"(hi));
    return r;
}
__device__ __forceinline__ float2 unpack2(ull v) {
    float2 r;
    asm("mov.b64 {%0, %1}, %2;" : "=f"(r.x), "=f"(r.y) : "l"(v));
    return r;
}

// ---------------- cp.async helpers ----------------
__device__ __forceinline__ void cp_async16(unsigned saddr, const float* g) {
    asm volatile("cp.async.cg.shared.global [%0], [%1], 16;" :: "r"(saddr), "l"(g));
}
__device__ __forceinline__ void cp_commit() {
    asm volatile("cp.async.commit_group;" ::: "memory");
}
__device__ __forceinline__ void cp_wait0() {
    asm volatile("cp.async.wait_group 0;" ::: "memory");
}

// ---------------- persistent backward Riccati (one CTA per batch, loop over t) ----------------
// Region A: V (64x66, symmetric) -> Aug (32x104) -> V_new.
// F via double-buffered cp.async 8-row chunks with boundary prefetches.
// Side-stream (warps 0-2): C(t-1) columns through a 4-deep register ring woven into
// the phase A/B n-loops -> c_back(t-1) + costpart(t-1) (prep_kernel eliminated).
static constexpr int AUG_S  = 104;                   // 8 mod 32 -> conflict-free GJ
static constexpr int V_S    = 66;                    // even (b64 aligned), mirror 2-way conflict
static constexpr int OFF_A  = 0;                     // max(64*66, 32*104) = 4224
static constexpr int A_FL   = 64 * V_S;
static constexpr int OFF_W  = OFF_A  + A_FL;         // 64x96 W = V F; Qxx park (col-major 66) after
static constexpr int OFF_QX = OFF_W  + 64 * 96;      // 32x64  saved Qux
static constexpr int OFF_q  = OFF_QX + 32 * 64;      // 64  (qx only)
static constexpr int OFF_v  = OFF_q  + 64;           // 64
static constexpr int OFF_kv = OFF_v  + 64;           // 32
static constexpr int OFF_di = OFF_kv + 32;           // 32
static constexpr int OFF_FC = OFF_di + 32;           // 2 x (8x96) double-buffered F chunks
static constexpr int OFF_XP = OFF_FC + 2 * 8 * 96;   // 96  xu(t-1)
static constexpr int OFF_CB = OFF_XP + 96;           // 96  c_back(t-1)
static constexpr int BK_FLOATS = OFF_CB + 96;        // 14336
static constexpr int BK_SMEM = BK_FLOATS * 4;        // 57344 B -> 4 CTAs/SM (4x(57344+1K)=228KB)

__global__ void __launch_bounds__(256, 4)
backward_kernel(const float* __restrict__ C, const float* __restrict__ F,
                const float* __restrict__ x, const float* __restrict__ u,
                const float* __restrict__ c) {
    extern __shared__ float sm[];
    float* sV   = sm + OFF_A;    // stride V_S
    float* sAug = sm + OFF_A;    // stride 104 (overlays V)
    float* sW   = sm + OFF_W;    // stride 96
    float* sQP  = sm + OFF_W;    // Qxx park, col-major stride 66 (overlays dead W)
    float* sQxS = sm + OFF_QX;   // stride 64
    float* sq   = sm + OFF_q;    // qx
    float* sv   = sm + OFF_v;
    float* skv  = sm + OFF_kv;
    float* sdin = sm + OFF_di;
    float* sFc  = sm + OFF_FC;   // 2 x 768 floats
    float* sxup = sm + OFF_XP;   // xu(t-1)
    float* scb  = sm + OFF_CB;   // c_back(t-1) -> consumed next iteration

    int b = blockIdx.x;
    int tid = threadIdx.x, lane = tid & 31, w = tid >> 5;
    unsigned fcbase = (unsigned)__cvta_generic_to_shared(sFc);

    // init V = 0, v = 0
    for (int i = tid; i < A_FL; i += 256) sV[i] = 0.f;
    if (tid < NS_) sv[tid] = 0.f;
    __syncthreads();

    for (int t = T_ - 1; t >= 0; t--) {
        size_t tb = (size_t)t * B_ + b;
        size_t tbp = tb - B_;                         // (t-1, b) — valid only for t>0
        const float* Cb = C + tb * SZ_ * SZ_;
        const float* Fb = F + tb * NS_ * SZ_;
        const float* Cp = C + (t > 0 ? tbp : tb) * (size_t)SZ_ * SZ_;
        const bool haveV = (t != T_ - 1);   // V==0 on the first backward step

        // side-stream inputs for t-1 (hidden behind phase A)
        float cpv = 0.f;
        if (t > 0 && tid < SZ_) {
            sxup[tid] = (tid < NS_) ? x[tbp * NS_ + tid] : u[tbp * NC_ + (tid - NS_)];
            cpv = c[tbp * SZ_ + tid];
        }
        // c_back(t) produced at the previous iteration (or the direct block below)
        float rq_base = 0.f;
        if (haveV && tid < SZ_) rq_base = scb[tid];

        if (!haveV) {
            // first backward step: direct dots for t (own) and t-1 (pipeline seed)
            __syncthreads();     // sxup visible
            {
                float part = 0.f;
                if (tid < SZ_) {
                    float dot0 = 0.f;
#pragma unroll 8
                    for (int j = 0; j < SZ_; j++) {
                        float xv = (j < NS_) ? x[tb * NS_ + j] : u[tb * NC_ + (j - NS_)];
                        dot0 += Cb[j * SZ_ + tid] * xv;
                    }
                    float cv = c[tb * SZ_ + tid];
                    rq_base = dot0 + cv;
                    float xus = (tid < NS_) ? x[tb * NS_ + tid] : u[tb * NC_ + (tid - NS_)];
                    part = xus * (0.5f * dot0 + cv);
#pragma unroll
                    for (int o = 16; o > 0; o >>= 1) part += __shfl_down_sync(0xffffffffu, part, o);
                    if (lane == 0) sFc[w] = part;
                }
            }
            __syncthreads();
            if (tid == 0) g_costpart[tb] = sFc[0] + sFc[1] + sFc[2];
            __syncthreads();
            if (t > 0) {
                float part = 0.f;
                if (tid < SZ_) {
                    float dot1 = 0.f;
#pragma unroll 8
                    for (int j = 0; j < SZ_; j++) dot1 += Cp[j * SZ_ + tid] * sxup[j];
                    scb[tid] = dot1 + cpv;
                    part = sxup[tid] * (0.5f * dot1 + cpv);
#pragma unroll
                    for (int o = 16; o > 0; o >>= 1) part += __shfl_down_sync(0xffffffffu, part, o);
                    if (lane == 0) sFc[w] = part;
                }
                __syncthreads();
                if (tid == 0) g_costpart[tbp] = sFc[0] + sFc[1] + sFc[2];
            }
        }

        // ---- Phase A: W = V F (async-pipelined F) + q accumulation + C(t-1) ring
        const bool act = haveV && (t > 0) && (tid < SZ_);
        float rC[4];
        float dotp = 0.f;
        float qacc = 0.f;
        if (haveV) {
            int m0 = w * 8;
            ull acc[4][3];
#pragma unroll
            for (int p = 0; p < 4; p++) { acc[p][0] = 0; acc[p][1] = 0; acc[p][2] = 0; }
            if (act) { rC[0] = Cp[tid]; rC[1] = Cp[96 + tid]; rC[2] = Cp[192 + tid]; rC[3] = Cp[288 + tid]; }
            // chunk 0 was prefetched at the previous iteration's post-GJ point
            for (int ch = 0; ch < 8; ch++) {
                cp_wait0();
                __syncthreads();
                if (tid < 192) {
                    if (ch < 7)
                        cp_async16(fcbase + ((ch + 1) & 1) * 3072 + tid * 16,
                                   Fb + (ch + 1) * 768 + tid * 4);
                    else  // tail: prefetch phase-B chunk 0 into buf 0
                        cp_async16(fcbase + tid * 16, Fb + tid * 4);
                }
                cp_commit();
                const float* fc = sFc + (ch & 1) * 768;
#pragma unroll
                for (int nn = 0; nn < 8; nn++) {
                    int n = ch * 8 + nn;
                    const float* fr = fc + nn * 96;
                    float b0 = fr[lane];
                    float b1 = fr[lane + 32];
                    float b2 = fr[lane + 64];
                    ull bb0 = pack2(b0, b0), bb1 = pack2(b1, b1), bb2 = pack2(b2, b2);
                    const ull* xv = (const ull*)&sV[n * V_S + m0];
#pragma unroll
                    for (int p = 0; p < 4; p++) {
                        ull xx = xv[p];
                        fma2(acc[p][0], xx, bb0);
                        fma2(acc[p][1], xx, bb1);
                        fma2(acc[p][2], xx, bb2);
                    }
                    if (tid < SZ_) qacc += fr[tid] * sv[n];
                    if (act) {
                        if (ch > 0 || nn >= 4) dotp += rC[nn & 3] * sxup[n - 4];
                        rC[nn & 3] = Cp[n * 96 + tid];
                    }
                }
            }
            // write W
#pragma unroll
            for (int p = 0; p < 4; p++) {
                int m = m0 + 2 * p;
                float2 c0 = unpack2(acc[p][0]);
                float2 c1 = unpack2(acc[p][1]);
                float2 c2 = unpack2(acc[p][2]);
                sW[m * 96 + lane]            = c0.x;
                sW[(m + 1) * 96 + lane]      = c0.y;
                sW[m * 96 + lane + 32]       = c1.x;
                sW[(m + 1) * 96 + lane + 32] = c1.y;
                sW[m * 96 + lane + 64]       = c2.x;
                sW[(m + 1) * 96 + lane + 64] = c2.y;
            }
        }
        float rq = qacc + rq_base;
        if (tid < NS_) sq[tid] = rq;
        __syncthreads();   // V dead; W visible; region A becomes Aug
        if (tid >= NS_ && tid < SZ_) sAug[(tid - NS_) * AUG_S + 96] = rq;   // qu

        // ---- Phase B (fused): Q = C + F^T W for ALL 96 rows in one async F pass.
        int i0 = w * 4;
        ull accx[4][2];
#pragma unroll
        for (int p = 0; p < 4; p++) { accx[p][0] = 0; accx[p][1] = 0; }
        {
            ull acc2[2][3];
#pragma unroll
            for (int p = 0; p < 2; p++) { acc2[p][0] = 0; acc2[p][1] = 0; acc2[p][2] = 0; }
            if (haveV) {
                // chunk 0 already in flight (phase-A tail prefetch)
                for (int ch = 0; ch < 8; ch++) {
                    cp_wait0();
                    __syncthreads();
                    if (ch < 7) {
                        if (tid < 192)
                            cp_async16(fcbase + ((ch + 1) & 1) * 3072 + tid * 16,
                                       Fb + (ch + 1) * 768 + tid * 4);
                        cp_commit();
                    }
                    const float* fc0 = sFc + (ch & 1) * 768;
#pragma unroll
                    for (int nn = 0; nn < 8; nn++) {
                        int n = ch * 8 + nn;
                        const float* wr = sW + n * 96;
                        float b0 = wr[lane];
                        float b1 = wr[lane + 32];
                        float b2 = wr[lane + 64];
                        ull bb0 = pack2(b0, b0), bb1 = pack2(b1, b1), bb2 = pack2(b2, b2);
                        const float* fc = fc0 + nn * 96;
                        ull xa0 = *(const ull*)(fc + 64 + i0);
                        ull xa1 = *(const ull*)(fc + 64 + i0 + 2);
                        fma2(acc2[0][0], xa0, bb0); fma2(acc2[0][1], xa0, bb1); fma2(acc2[0][2], xa0, bb2);
                        fma2(acc2[1][0], xa1, bb0); fma2(acc2[1][1], xa1, bb1); fma2(acc2[1][2], xa1, bb2);
#pragma unroll
                        for (int pp = 0; pp < 4; pp++) {
                            ull xx = *(const ull*)(fc + 2 * (w + 8 * pp));
                            fma2(accx[pp][0], xx, bb0);
                            if (pp >= 2) fma2(accx[pp][1], xx, bb1);
                        }
                        if (act) {
                            if (ch < 4 || (ch == 4 && nn < 4)) dotp += rC[nn & 3] * sxup[60 + n];
                            if (ch < 4) rC[nn & 3] = Cp[(64 + n) * 96 + tid];
                        }
                    }
                }
                // side-stream finalize: c_back(t-1) + costpart(t-1) partials
                if (act) {
                    scb[tid] = dotp + cpv;
                    float part = sxup[tid] * (0.5f * dotp + cpv);
#pragma unroll
                    for (int o = 16; o > 0; o >>= 1) part += __shfl_down_sync(0xffffffffu, part, o);
                    if (lane == 0) sFc[w] = part;   // buf0[0..2]: last read was ch=6, sealed by ch=7 barrier
                }
            }
            // GEMM2 epilogue -> Aug / QxS (+ C rows 64..95)
#pragma unroll
            for (int p = 0; p < 2; p++) {
                int i = i0 + 2 * p;
                float2 c0 = unpack2(acc2[p][0]);   // s = lane       (Qux)
                float2 c1 = unpack2(acc2[p][1]);   // s = lane + 32  (Qux)
                float2 c2 = unpack2(acc2[p][2]);   // s = lane + 64  (Quu)
                float v00 = c0.x + Cb[(64 + i) * 96 + lane];
                float v10 = c0.y + Cb[(64 + i + 1) * 96 + lane];
                float v01 = c1.x + Cb[(64 + i) * 96 + lane + 32];
                float v11 = c1.y + Cb[(64 + i + 1) * 96 + lane + 32];
                float v02 = c2.x + Cb[(64 + i) * 96 + lane + 64];
                float v12 = c2.y + Cb[(64 + i + 1) * 96 + lane + 64];
                sQxS[i * 64 + lane] = v00;            sAug[i * AUG_S + 32 + lane] = v00;
                sQxS[(i + 1) * 64 + lane] = v10;      sAug[(i + 1) * AUG_S + 32 + lane] = v10;
                sQxS[i * 64 + lane + 32] = v01;       sAug[i * AUG_S + 64 + lane] = v01;
                sQxS[(i + 1) * 64 + lane + 32] = v11; sAug[(i + 1) * AUG_S + 64 + lane] = v11;
                sAug[i * AUG_S + lane] = v02;
                sAug[(i + 1) * AUG_S + lane] = v12;
            }
        }
        __syncthreads();   // W dead from here; park Qxx accumulators in its region

        if (haveV && t > 0 && tid == 0)
            g_costpart[tbp] = sFc[0] + sFc[1] + sFc[2];

        // park accx (col-major, stride 66, conflict-free b64) — frees regs across GJ
#pragma unroll
        for (int pp = 0; pp < 4; pp++) {
            int i = 2 * (w + 8 * pp);
            *(ull*)&sQP[lane * 66 + i] = accx[pp][0];
            if (pp >= 2) *(ull*)&sQP[(lane + 32) * 66 + i] = accx[pp][1];
        }

        // ---- Gauss-Jordan (unnormalized; SPD, no pivoting; 1 barrier/pivot)
        {
            int r = tid >> 3, sub = tid & 7;
            for (int kp = 0; kp < 32; kp++) {
                if (r != kp) {
                    float f = __fdividef(sAug[r * AUG_S + kp], sAug[kp * AUG_S + kp]);
                    for (int j = kp + 1 + sub; j <= 96; j += 8)
                        sAug[r * AUG_S + j] -= f * sAug[kp * AUG_S + j];
                }
                __syncthreads();
            }
        }

        // boundary prefetch: next t's phase-A chunk 0 (lands during K/V_new epilogue)
        if (t > 0) {
            if (tid < 192) cp_async16(fcbase + tid * 16, Fb - (size_t)B_ * NS_ * SZ_ + tid * 4);
            cp_commit();
        }

        // diag inverses, k
        if (tid < 32) {
            float di = 1.0f / sAug[tid * AUG_S + tid];
            sdin[tid] = di;
            float kv = -sAug[tid * AUG_S + 96] * di;
            skv[tid] = kv;
            g_kv[tb * NC_ + tid] = kv;
        }
        __syncthreads();

        // K -> global only (smem K folded into V_new reads of Aug)
        {
            float* Kg = g_K + tb * NC_ * NS_;
            for (int i = tid; i < NC_ * NS_; i += 256) {
                int m = i >> 6, j = i & 63;
                Kg[i] = -sAug[m * AUG_S + 32 + j] * sdin[m];
            }
        }

        // ---- V_new finalize: reload Qxx partials, += Qux^T K, add C, mirror-store.
        {
            ull acc0[4]; ull acc1[2];
#pragma unroll
            for (int pp = 0; pp < 4; pp++) {
                int i = 2 * (w + 8 * pp);
                acc0[pp] = *(const ull*)&sQP[lane * 66 + i];
                if (pp >= 2) acc1[pp - 2] = *(const ull*)&sQP[(lane + 32) * 66 + i];
            }
#pragma unroll 4
            for (int m = 0; m < 32; m++) {
                float nd = -sdin[m];
                float b0 = nd * sAug[m * AUG_S + 32 + lane];        // K[m][lane]
                float b1 = nd * sAug[m * AUG_S + 64 + lane];        // K[m][lane+32]
                ull bb0 = pack2(b0, b0), bb1 = pack2(b1, b1);
#pragma unroll
                for (int pp = 0; pp < 4; pp++) {
                    ull xx = *(const ull*)&sQxS[m * 64 + 2 * (w + 8 * pp)];
                    fma2(acc0[pp], xx, bb0);
                    if (pp >= 2) fma2(acc1[pp - 2], xx, bb1);
                }
            }
            // v_new partial (reads sq/sQxS/skv — outside region A)
            float vnew = 0.f;
            if (tid < NS_) {
                float a = sq[tid];
#pragma unroll 4
                for (int m = 0; m < 32; m++) a += sQxS[m * 64 + tid] * skv[m];
                vnew = a;
            }
            // add C (LDGs issued before the barrier so latency overlaps the wait)
            float sv0[4], sv1[4], sw0v[2], sw1v[2];
#pragma unroll
            for (int pp = 0; pp < 4; pp++) {
                int i = 2 * (w + 8 * pp);
                float2 c0 = unpack2(acc0[pp]);
                sv0[pp] = c0.x + Cb[i * 96 + lane];
                sv1[pp] = c0.y + Cb[(i + 1) * 96 + lane];
                if (pp >= 2) {
                    float2 c1 = unpack2(acc1[pp - 2]);
                    sw0v[pp - 2] = c1.x + Cb[i * 96 + lane + 32];
                    sw1v[pp - 2] = c1.y + Cb[(i + 1) * 96 + lane + 32];
                }
            }
            __syncthreads();   // ALL Aug/QP reads complete before region A is overwritten

#pragma unroll
            for (int pp = 0; pp < 4; pp++) {
                int i = 2 * (w + 8 * pp);
                int j = lane;
                if (j <= i)     sV[i * V_S + j]       = sv0[pp];
                if (j <  i)     sV[j * V_S + i]       = sv0[pp];
                if (j <= i + 1) sV[(i + 1) * V_S + j] = sv1[pp];
                if (j <  i + 1) sV[j * V_S + i + 1]   = sv1[pp];
                if (pp >= 2) {
                    int j2 = lane + 32;
                    if (j2 <= i)     sV[i * V_S + j2]       = sw0v[pp - 2];
                    if (j2 <  i)     sV[j2 * V_S + i]       = sw0v[pp - 2];
                    if (j2 <= i + 1) sV[(i + 1) * V_S + j2] = sw1v[pp - 2];
                    if (j2 <  i + 1) sV[j2 * V_S + i + 1]   = sw1v[pp - 2];
                }
            }
            if (tid < NS_) sv[tid] = vnew;
        }
        __syncthreads();
    }
}

// ---------------- rollout: base (alpha=0) and direction trajectories ----------------
__global__ void rollout_kernel(const float* __restrict__ x, const float* __restrict__ u,
                               const float* __restrict__ x_init, const float* __restrict__ F) {
    int b = blockIdx.x;
    int tid = threadIdx.x;   // 128
    __shared__ float sF[64 * 97];
    __shared__ float sK[32 * 65];
    __shared__ float sk[32], su[32], sxn[64];
    __shared__ float nx0[64], dx0[64], dnx[64];
    __shared__ float sz0[96], szd[96];
    __shared__ float nxn[64], dnxn[64];

    if (tid < 64) { nx0[tid] = x_init[b * 64 + tid]; dx0[tid] = 0.f; dnx[tid] = 0.f; }
    __syncthreads();

    for (int t = 0; t < T_; t++) {
        size_t tb = (size_t)t * B_ + b;
        const float* Fb = F + tb * NS_ * SZ_;
        const float4* F4 = (const float4*)Fb;
        for (int i4 = tid; i4 < NS_ * SZ_ / 4; i4 += 128) {
            float4 v = F4[i4];
            int e = i4 * 4; int r = e / 96; int cc = e % 96;
            float* dst = &sF[r * 97 + cc];
            dst[0] = v.x; dst[1] = v.y; dst[2] = v.z; dst[3] = v.w;
        }
        const float4* K4 = (const float4*)(g_K + tb * NC_ * NS_);
        for (int i4 = tid; i4 < NC_ * NS_ / 4; i4 += 128) {
            float4 v = K4[i4];
            int e = i4 * 4; int r = e >> 6; int cc = e & 63;
            float* dst = &sK[r * 65 + cc];
            dst[0] = v.x; dst[1] = v.y; dst[2] = v.z; dst[3] = v.w;
        }
        if (tid < NC_) { sk[tid] = g_kv[tb * NC_ + tid]; su[tid] = u[tb * NC_ + tid]; }
        int tn = (t < T_ - 1) ? t + 1 : T_ - 1;
        if (tid < NS_) sxn[tid] = x[((size_t)tn * B_ + b) * NS_ + tid];
        __syncthreads();

        // controls
        if (tid < NC_) {
            float a0 = su[tid], a1 = sk[tid];
#pragma unroll 8
            for (int n = 0; n < 64; n++) { float kk = sK[tid * 65 + n]; a0 += kk * dx0[n]; a1 += kk * dnx[n]; }
            sz0[64 + tid] = a0; szd[64 + tid] = a1;
        }
        if (tid < NS_) { sz0[tid] = nx0[tid]; szd[tid] = dnx[tid]; }
        __syncthreads();

        // record entry state+control
        if (tid < SZ_) { g_z0[tb * SZ_ + tid] = sz0[tid]; g_dz[tb * SZ_ + tid] = szd[tid]; }

        // next state
        if (tid < NS_) {
            float a0 = 0.f, a1 = 0.f;
            const float* fr = &sF[tid * 97];
#pragma unroll 8
            for (int s = 0; s < 96; s++) { float fv = fr[s]; a0 += fv * sz0[s]; a1 += fv * szd[s]; }
            nxn[tid] = a0; dnxn[tid] = a1;
        }
        __syncthreads();
        if (tid < NS_) { nx0[tid] = nxn[tid]; dx0[tid] = nxn[tid] - sxn[tid]; dnx[tid] = dnxn[tid]; }
        __syncthreads();
    }
}

// ---------------- cost quadratic coefficients: cost(a) = q0 + a q1 + a^2 q2 ----------------
__global__ void coef_kernel(const float* __restrict__ C, const float* __restrict__ c) {
    int tb = blockIdx.x;
    int tid = threadIdx.x;   // 96 threads, 3 warps
    __shared__ float sz[SZ_], sd[SZ_];
    __shared__ float sw0[3], sw1[3], sw2[3];

    sz[tid] = g_z0[(size_t)tb * SZ_ + tid];
    sd[tid] = g_dz[(size_t)tb * SZ_ + tid];
    __syncthreads();

    const float* col = C + (size_t)tb * SZ_ * SZ_ + tid;
    float y0 = 0.f, yd = 0.f;
#pragma unroll 8
    for (int j = 0; j < SZ_; j++) {
        float cij = col[j * SZ_];
        y0 += cij * sz[j];
        yd += cij * sd[j];
    }
    float cv = c[(size_t)tb * SZ_ + tid];
    float p0 = sz[tid] * (0.5f * y0 + cv);
    float p1 = sd[tid] * (y0 + cv);
    float p2 = 0.5f * sd[tid] * yd;

#pragma unroll
    for (int o = 16; o > 0; o >>= 1) {
        p0 += __shfl_down_sync(0xffffffffu, p0, o);
        p1 += __shfl_down_sync(0xffffffffu, p1, o);
        p2 += __shfl_down_sync(0xffffffffu, p2, o);
    }
    if ((tid & 31) == 0) { int w = tid >> 5; sw0[w] = p0; sw1[w] = p1; sw2[w] = p2; }
    __syncthreads();
    if (tid == 0) {
        g_q0[tb] = sw0[0] + sw0[1] + sw0[2];
        g_q1[tb] = sw1[0] + sw1[1] + sw1[2];
        g_q2[tb] = sw2[0] + sw2[1] + sw2[2];
    }
}

// ---------------- line search resolve + cost output ----------------
__global__ void ls_kernel(float* __restrict__ out_cost) {
    int b = threadIdx.x;  // 512
    float old = 0.f, A0 = 0.f, A1 = 0.f, A2 = 0.f;
    for (int t = 0; t < T_; t++) {
        int idx = t * B_ + b;
        old += g_costpart[idx];
        A0 += g_q0[idx]; A1 += g_q1[idx]; A2 += g_q2[idx];
    }
    float alpha = 1.f;
#pragma unroll
    for (int i = 0; i < 3; i++) {
        float cst = A0 + alpha * (A1 + alpha * A2);
        if (cst > old) alpha *= 0.5f;
    }
    float cur = A0 + alpha * (A1 + alpha * A2);
    g_alpha[b] = alpha;
    out_cost[b] = cur;
}

// ---------------- final outputs: new_x, new_u ----------------
__global__ void out_kernel(float* __restrict__ out) {
    size_t total = (size_t)T_ * B_ * SZ_;
    for (size_t idx = blockIdx.x * (size_t)blockDim.x + threadIdx.x; idx < total;
         idx += (size_t)gridDim.x * blockDim.x) {
        size_t tb = idx / SZ_;
        int s = (int)(idx % SZ_);
        int b = (int)(tb % B_);
        float val = g_z0[idx] + g_alpha[b] * g_dz[idx];
        if (s < NS_) out[tb * NS_ + s] = val;
        else         out[(size_t)T_ * B_ * NS_ + tb * NC_ + (s - NS_)] = val;
    }
}

// ---------------- launch ----------------
extern "C" void kernel_launch(void* const* d_in, const int* in_sizes, int n_in,
                              void* d_out, int out_size) {
    const float *x = nullptr, *u = nullptr, *xi = nullptr, *C = nullptr, *c = nullptr, *F = nullptr;
    for (int i = 0; i < n_in; i++) {
        long long s = in_sizes[i];
        const float* p = (const float*)d_in[i];
        if      (s == (long long)T_ * B_ * SZ_ * SZ_) C = p;
        else if (s == (long long)T_ * B_ * NS_ * SZ_) F = p;
        else if (s == (long long)T_ * B_ * SZ_)       c = p;
        else if (s == (long long)T_ * B_ * NS_)       x = p;
        else if (s == (long long)T_ * B_ * NC_)       u = p;
        else if (s == (long long)B_ * NS_)            xi = p;
    }
    float* out = (float*)d_out;

    cudaFuncSetAttribute(backward_kernel, cudaFuncAttributeMaxDynamicSharedMemorySize, BK_SMEM);

    backward_kernel<<<B_, 256, BK_SMEM>>>(C, F, x, u, c);
    rollout_kernel<<<B_, 128>>>(x, u, xi, F);
    coef_kernel<<<T_ * B_, 96>>>(C, c);
    ls_kernel<<<1, B_>>>(out + (size_t)T_ * B_ * (NS_ + NC_));
    out_kernel<<<4096, 256>>>(out);
}

// round 16
// speedup vs baseline: 1.0602x; 1.0602x over previous
#include <cuda_runtime.h>
#include <cstddef>

static constexpr int T_  = 32;
static constexpr int B_  = 512;
static constexpr int NS_ = 64;
static constexpr int NC_ = 32;
static constexpr int SZ_ = 96;   // NS + NC

using ull = unsigned long long;

// ---------------- scratch (static device globals; no allocation) ----------------
__device__ float g_cback[(size_t)T_ * B_ * SZ_];      // C@xu + c
__device__ float g_costpart[T_ * B_];                 // per (t,b) old-cost contribution
__device__ float g_q0[T_ * B_];
__device__ float g_q1[T_ * B_];
__device__ float g_q2[T_ * B_];
__device__ float g_K[(size_t)T_ * B_ * NC_ * NS_];    // gains
__device__ float g_kv[(size_t)T_ * B_ * NC_];
__device__ float g_z0[(size_t)T_ * B_ * SZ_];         // base rollout [nx;nu] (alpha=0)
__device__ float g_dz[(size_t)T_ * B_ * SZ_];         // d/dalpha of rollout

// ---------------- packed f32x2 helpers ----------------
__device__ __forceinline__ void fma2(ull& acc, ull x, ull b) {
    asm("fma.rn.f32x2 %0, %1, %2, %0;" : "+l"(acc) : "l"(x), "l"(b));
}
__device__ __forceinline__ ull pack2(float lo, float hi) {
    ull r;
    asm("mov.b64 %0, {%1, %2};" : "=l"(r) : "f"(lo), "f"(hi));
    return r;
}
__device__ __forceinline__ float2 unpack2(ull v) {
    float2 r;
    asm("mov.b64 {%0, %1}, %2;" : "=f"(r.x), "=f"(r.y) : "l"(v));
    return r;
}

// ---------------- cp.async helpers ----------------
__device__ __forceinline__ void cp_async16(unsigned saddr, const float* g) {
    asm volatile("cp.async.cg.shared.global [%0], [%1], 16;" :: "r"(saddr), "l"(g));
}
__device__ __forceinline__ void cp_commit() {
    asm volatile("cp.async.commit_group;" ::: "memory");
}
__device__ __forceinline__ void cp_wait0() {
    asm volatile("cp.async.wait_group 0;" ::: "memory");
}

// ---------------- prep: c_back = C@xu + c ; old-cost partials ----------------
__global__ void prep_kernel(const float* __restrict__ x, const float* __restrict__ u,
                            const float* __restrict__ C, const float* __restrict__ c) {
    int tb = blockIdx.x;                 // t*B + b
    int tid = threadIdx.x;               // 96 threads, 3 warps
    __shared__ float sxu[SZ_];
    __shared__ float swp[3];

    if (tid < NS_)      sxu[tid] = x[(size_t)tb * NS_ + tid];
    else if (tid < SZ_) sxu[tid] = u[(size_t)tb * NC_ + (tid - NS_)];
    __syncthreads();

    const float* col = C + (size_t)tb * SZ_ * SZ_ + tid;
    float acc = 0.f;
#pragma unroll 8
    for (int j = 0; j < SZ_; j++) acc += col[j * SZ_] * sxu[j];
    float cv = c[(size_t)tb * SZ_ + tid];
    g_cback[(size_t)tb * SZ_ + tid] = acc + cv;
    float part = sxu[tid] * (0.5f * acc + cv);

#pragma unroll
    for (int o = 16; o > 0; o >>= 1) part += __shfl_down_sync(0xffffffffu, part, o);
    if ((tid & 31) == 0) swp[tid >> 5] = part;
    __syncthreads();
    if (tid == 0) g_costpart[tb] = swp[0] + swp[1] + swp[2];
}

// ---------------- persistent backward Riccati (one CTA per batch, loop over t) ----------------
// Region A: V (64x66, symmetric) -> Aug (32x104) -> V_new.
// F streamed via double-buffered cp.async 8-row chunks.
// GEMM2 + Qxx(FtW) fused into one F pass; Qxx triangle held in registers across GJ.
static constexpr int AUG_S  = 104;                   // 8 mod 32 -> conflict-free GJ
static constexpr int V_S    = 66;                    // even (b64 aligned), mirror 2-way conflict
static constexpr int OFF_A  = 0;                     // max(64*66, 32*104) = 4224
static constexpr int A_FL   = 64 * V_S;
static constexpr int OFF_W  = OFF_A  + A_FL;         // 64x96  W = V F
static constexpr int OFF_QX = OFF_W  + 64 * 96;      // 32x64  saved Qux
static constexpr int OFF_q  = OFF_QX + 32 * 64;      // 64  (qx only)
static constexpr int OFF_v  = OFF_q  + 64;           // 64
static constexpr int OFF_kv = OFF_v  + 64;           // 32
static constexpr int OFF_di = OFF_kv + 32;           // 32
static constexpr int OFF_FC = OFF_di + 32;           // 2 x (8x96) double-buffered F chunks
static constexpr int BK_FLOATS = OFF_FC + 2 * 8 * 96;  // 14144
static constexpr int BK_SMEM = BK_FLOATS * 4;        // 56576 B -> 4 CTAs/SM

__global__ void __launch_bounds__(256, 4)
backward_kernel(const float* __restrict__ C, const float* __restrict__ F) {
    extern __shared__ float sm[];
    float* sV   = sm + OFF_A;    // stride V_S
    float* sAug = sm + OFF_A;    // stride 104 (overlays V)
    float* sW   = sm + OFF_W;    // stride 96
    float* sQxS = sm + OFF_QX;   // stride 64
    float* sq   = sm + OFF_q;    // qx
    float* sv   = sm + OFF_v;
    float* skv  = sm + OFF_kv;
    float* sdin = sm + OFF_di;
    float* sFc  = sm + OFF_FC;   // 2 x 768 floats

    int b = blockIdx.x;
    int tid = threadIdx.x, lane = tid & 31, w = tid >> 5;
    unsigned fcbase = (unsigned)__cvta_generic_to_shared(sFc);

    // init V = 0, v = 0
    for (int i = tid; i < A_FL; i += 256) sV[i] = 0.f;
    if (tid < NS_) sv[tid] = 0.f;
    __syncthreads();

    for (int t = T_ - 1; t >= 0; t--) {
        size_t tb = (size_t)t * B_ + b;
        const float* Cb = C + tb * SZ_ * SZ_;
        const float* Fb = F + tb * NS_ * SZ_;
        const bool haveV = (t != T_ - 1);   // V==0 on the first backward step

        // ---- Phase A: W = V F (async-pipelined F) + q accumulation
        float qacc = 0.f;
        if (haveV) {
            int m0 = w * 8;
            ull acc[4][3];
#pragma unroll
            for (int p = 0; p < 4; p++) { acc[p][0] = 0; acc[p][1] = 0; acc[p][2] = 0; }
            // prefetch chunk 0 -> buf 0
            if (tid < 192) cp_async16(fcbase + tid * 16, Fb + tid * 4);
            cp_commit();
            for (int ch = 0; ch < 8; ch++) {
                cp_wait0();
                __syncthreads();
                if (ch < 7) {
                    if (tid < 192)
                        cp_async16(fcbase + ((ch + 1) & 1) * 3072 + tid * 16,
                                   Fb + (ch + 1) * 768 + tid * 4);
                    cp_commit();
                }
                const float* fc = sFc + (ch & 1) * 768;
#pragma unroll
                for (int nn = 0; nn < 8; nn++) {
                    int n = ch * 8 + nn;
                    const float* fr = fc + nn * 96;
                    float b0 = fr[lane];
                    float b1 = fr[lane + 32];
                    float b2 = fr[lane + 64];
                    ull bb0 = pack2(b0, b0), bb1 = pack2(b1, b1), bb2 = pack2(b2, b2);
                    const ull* xv = (const ull*)&sV[n * V_S + m0];
#pragma unroll
                    for (int p = 0; p < 4; p++) {
                        ull xx = xv[p];
                        fma2(acc[p][0], xx, bb0);
                        fma2(acc[p][1], xx, bb1);
                        fma2(acc[p][2], xx, bb2);
                    }
                    if (tid < SZ_) qacc += fr[tid] * sv[n];
                }
            }
            // write W
#pragma unroll
            for (int p = 0; p < 4; p++) {
                int m = m0 + 2 * p;
                float2 c0 = unpack2(acc[p][0]);
                float2 c1 = unpack2(acc[p][1]);
                float2 c2 = unpack2(acc[p][2]);
                sW[m * 96 + lane]            = c0.x;
                sW[(m + 1) * 96 + lane]      = c0.y;
                sW[m * 96 + lane + 32]       = c1.x;
                sW[(m + 1) * 96 + lane + 32] = c1.y;
                sW[m * 96 + lane + 64]       = c2.x;
                sW[(m + 1) * 96 + lane + 64] = c2.y;
            }
        }
        float rq = 0.f;
        if (tid < SZ_) {
            rq = qacc + g_cback[tb * SZ_ + tid];
            if (tid < NS_) sq[tid] = rq;
        }
        __syncthreads();   // V dead; W visible; region A becomes Aug
        if (tid >= NS_ && tid < SZ_) sAug[(tid - NS_) * AUG_S + 96] = rq;   // qu

        // ---- Phase B (fused): Q = C + F^T W for ALL 96 rows in one async F pass.
        // Rows 64..95 -> Aug/QxS now; rows 0..63 triangle -> registers (accx).
        int i0 = w * 4;
        ull accx[4][2];
#pragma unroll
        for (int p = 0; p < 4; p++) { accx[p][0] = 0; accx[p][1] = 0; }
        {
            ull acc2[2][3];
#pragma unroll
            for (int p = 0; p < 2; p++) { acc2[p][0] = 0; acc2[p][1] = 0; acc2[p][2] = 0; }
            if (haveV) {
                if (tid < 192) cp_async16(fcbase + tid * 16, Fb + tid * 4);
                cp_commit();
                for (int ch = 0; ch < 8; ch++) {
                    cp_wait0();
                    __syncthreads();
                    if (ch < 7) {
                        if (tid < 192)
                            cp_async16(fcbase + ((ch + 1) & 1) * 3072 + tid * 16,
                                       Fb + (ch + 1) * 768 + tid * 4);
                        cp_commit();
                    }
                    const float* fc0 = sFc + (ch & 1) * 768;
#pragma unroll
                    for (int nn = 0; nn < 8; nn++) {
                        int n = ch * 8 + nn;
                        const float* wr = sW + n * 96;
                        float b0 = wr[lane];
                        float b1 = wr[lane + 32];
                        float b2 = wr[lane + 64];
                        ull bb0 = pack2(b0, b0), bb1 = pack2(b1, b1), bb2 = pack2(b2, b2);
                        const float* fc = fc0 + nn * 96;
                        ull xa0 = *(const ull*)(fc + 64 + i0);
                        ull xa1 = *(const ull*)(fc + 64 + i0 + 2);
                        fma2(acc2[0][0], xa0, bb0); fma2(acc2[0][1], xa0, bb1); fma2(acc2[0][2], xa0, bb2);
                        fma2(acc2[1][0], xa1, bb0); fma2(acc2[1][1], xa1, bb1); fma2(acc2[1][2], xa1, bb2);
#pragma unroll
                        for (int pp = 0; pp < 4; pp++) {
                            ull xx = *(const ull*)(fc + 2 * (w + 8 * pp));
                            fma2(accx[pp][0], xx, bb0);
                            if (pp >= 2) fma2(accx[pp][1], xx, bb1);
                        }
                    }
                }
            }
            // GEMM2 epilogue -> Aug / QxS (+ C rows 64..95)
#pragma unroll
            for (int p = 0; p < 2; p++) {
                int i = i0 + 2 * p;
                float2 c0 = unpack2(acc2[p][0]);   // s = lane       (Qux)
                float2 c1 = unpack2(acc2[p][1]);   // s = lane + 32  (Qux)
                float2 c2 = unpack2(acc2[p][2]);   // s = lane + 64  (Quu)
                float v00 = c0.x + Cb[(64 + i) * 96 + lane];
                float v10 = c0.y + Cb[(64 + i + 1) * 96 + lane];
                float v01 = c1.x + Cb[(64 + i) * 96 + lane + 32];
                float v11 = c1.y + Cb[(64 + i + 1) * 96 + lane + 32];
                float v02 = c2.x + Cb[(64 + i) * 96 + lane + 64];
                float v12 = c2.y + Cb[(64 + i + 1) * 96 + lane + 64];
                sQxS[i * 64 + lane] = v00;            sAug[i * AUG_S + 32 + lane] = v00;
                sQxS[(i + 1) * 64 + lane] = v10;      sAug[(i + 1) * AUG_S + 32 + lane] = v10;
                sQxS[i * 64 + lane + 32] = v01;       sAug[i * AUG_S + 64 + lane] = v01;
                sQxS[(i + 1) * 64 + lane + 32] = v11; sAug[(i + 1) * AUG_S + 64 + lane] = v11;
                sAug[i * AUG_S + lane] = v02;
                sAug[(i + 1) * AUG_S + lane] = v12;
            }
        }
        __syncthreads();

        // ---- Gauss-Jordan (unnormalized; SPD, no pivoting; 1 barrier/pivot)
        {
            int r = tid >> 3, sub = tid & 7;
            for (int kp = 0; kp < 32; kp++) {
                if (r != kp) {
                    float f = __fdividef(sAug[r * AUG_S + kp], sAug[kp * AUG_S + kp]);
                    for (int j = kp + 1 + sub; j <= 96; j += 8)
                        sAug[r * AUG_S + j] -= f * sAug[kp * AUG_S + j];
                }
                __syncthreads();
            }
        }

        // diag inverses, k
        if (tid < 32) {
            float di = 1.0f / sAug[tid * AUG_S + tid];
            sdin[tid] = di;
            float kv = -sAug[tid * AUG_S + 96] * di;
            skv[tid] = kv;
            g_kv[tb * NC_ + tid] = kv;
        }
        __syncthreads();

        // K -> global only (smem K folded into V_new reads of Aug)
        {
            float* Kg = g_K + tb * NC_ * NS_;
            for (int i = tid; i < NC_ * NS_; i += 256) {
                int m = i >> 6, j = i & 63;
                Kg[i] = -sAug[m * AUG_S + 32 + j] * sdin[m];
            }
        }

        // ---- V_new finalize: accx += Qux^T K; add C; mirror-store lower triangle.
        {
#pragma unroll 4
            for (int m = 0; m < 32; m++) {
                float nd = -sdin[m];
                float b0 = nd * sAug[m * AUG_S + 32 + lane];        // K[m][lane]
                float b1 = nd * sAug[m * AUG_S + 64 + lane];        // K[m][lane+32]
                ull bb0 = pack2(b0, b0), bb1 = pack2(b1, b1);
#pragma unroll
                for (int pp = 0; pp < 4; pp++) {
                    ull xx = *(const ull*)&sQxS[m * 64 + 2 * (w + 8 * pp)];
                    fma2(accx[pp][0], xx, bb0);
                    if (pp >= 2) fma2(accx[pp][1], xx, bb1);
                }
            }
            // v_new partial (reads sq/sQxS/skv — outside region A)
            float vnew = 0.f;
            if (tid < NS_) {
                float a = sq[tid];
#pragma unroll 4
                for (int m = 0; m < 32; m++) a += sQxS[m * 64 + tid] * skv[m];
                vnew = a;
            }
            // add C (LDGs issued before the barrier so latency overlaps the wait)
            float sv0[4], sv1[4], sw0v[2], sw1v[2];
#pragma unroll
            for (int pp = 0; pp < 4; pp++) {
                int i = 2 * (w + 8 * pp);
                float2 c0 = unpack2(accx[pp][0]);
                sv0[pp] = c0.x + Cb[i * 96 + lane];
                sv1[pp] = c0.y + Cb[(i + 1) * 96 + lane];
                if (pp >= 2) {
                    float2 c1 = unpack2(accx[pp][1]);
                    sw0v[pp - 2] = c1.x + Cb[i * 96 + lane + 32];
                    sw1v[pp - 2] = c1.y + Cb[(i + 1) * 96 + lane + 32];
                }
            }
            __syncthreads();   // ALL Aug reads complete before region A is overwritten

#pragma unroll
            for (int pp = 0; pp < 4; pp++) {
                int i = 2 * (w + 8 * pp);
                int j = lane;
                if (j <= i)     sV[i * V_S + j]       = sv0[pp];
                if (j <  i)     sV[j * V_S + i]       = sv0[pp];
                if (j <= i + 1) sV[(i + 1) * V_S + j] = sv1[pp];
                if (j <  i + 1) sV[j * V_S + i + 1]   = sv1[pp];
                if (pp >= 2) {
                    int j2 = lane + 32;
                    if (j2 <= i)     sV[i * V_S + j2]       = sw0v[pp - 2];
                    if (j2 <  i)     sV[j2 * V_S + i]       = sw0v[pp - 2];
                    if (j2 <= i + 1) sV[(i + 1) * V_S + j2] = sw1v[pp - 2];
                    if (j2 <  i + 1) sV[j2 * V_S + i + 1]   = sw1v[pp - 2];
                }
            }
            if (tid < NS_) sv[tid] = vnew;
        }
        __syncthreads();
    }
}

// ---------------- rollout: base (alpha=0) and direction trajectories ----------------
__global__ void rollout_kernel(const float* __restrict__ x, const float* __restrict__ u,
                               const float* __restrict__ x_init, const float* __restrict__ F) {
    int b = blockIdx.x;
    int tid = threadIdx.x;   // 128
    __shared__ float sF[64 * 97];
    __shared__ float sK[32 * 65];
    __shared__ float sk[32], su[32], sxn[64];
    __shared__ float nx0[64], dx0[64], dnx[64];
    __shared__ float sz0[96], szd[96];
    __shared__ float nxn[64], dnxn[64];

    if (tid < 64) { nx0[tid] = x_init[b * 64 + tid]; dx0[tid] = 0.f; dnx[tid] = 0.f; }
    __syncthreads();

    for (int t = 0; t < T_; t++) {
        size_t tb = (size_t)t * B_ + b;
        const float* Fb = F + tb * NS_ * SZ_;
        const float4* F4 = (const float4*)Fb;
        for (int i4 = tid; i4 < NS_ * SZ_ / 4; i4 += 128) {
            float4 v = F4[i4];
            int e = i4 * 4; int r = e / 96; int cc = e % 96;
            float* dst = &sF[r * 97 + cc];
            dst[0] = v.x; dst[1] = v.y; dst[2] = v.z; dst[3] = v.w;
        }
        const float4* K4 = (const float4*)(g_K + tb * NC_ * NS_);
        for (int i4 = tid; i4 < NC_ * NS_ / 4; i4 += 128) {
            float4 v = K4[i4];
            int e = i4 * 4; int r = e >> 6; int cc = e & 63;
            float* dst = &sK[r * 65 + cc];
            dst[0] = v.x; dst[1] = v.y; dst[2] = v.z; dst[3] = v.w;
        }
        if (tid < NC_) { sk[tid] = g_kv[tb * NC_ + tid]; su[tid] = u[tb * NC_ + tid]; }
        int tn = (t < T_ - 1) ? t + 1 : T_ - 1;
        if (tid < NS_) sxn[tid] = x[((size_t)tn * B_ + b) * NS_ + tid];
        __syncthreads();

        // controls
        if (tid < NC_) {
            float a0 = su[tid], a1 = sk[tid];
#pragma unroll 8
            for (int n = 0; n < 64; n++) { float kk = sK[tid * 65 + n]; a0 += kk * dx0[n]; a1 += kk * dnx[n]; }
            sz0[64 + tid] = a0; szd[64 + tid] = a1;
        }
        if (tid < NS_) { sz0[tid] = nx0[tid]; szd[tid] = dnx[tid]; }
        __syncthreads();

        // record entry state+control
        if (tid < SZ_) { g_z0[tb * SZ_ + tid] = sz0[tid]; g_dz[tb * SZ_ + tid] = szd[tid]; }

        // next state
        if (tid < NS_) {
            float a0 = 0.f, a1 = 0.f;
            const float* fr = &sF[tid * 97];
#pragma unroll 8
            for (int s = 0; s < 96; s++) { float fv = fr[s]; a0 += fv * sz0[s]; a1 += fv * szd[s]; }
            nxn[tid] = a0; dnxn[tid] = a1;
        }
        __syncthreads();
        if (tid < NS_) { nx0[tid] = nxn[tid]; dx0[tid] = nxn[tid] - sxn[tid]; dnx[tid] = dnxn[tid]; }
        __syncthreads();
    }
}

// ---------------- cost quadratic coefficients: cost(a) = q0 + a q1 + a^2 q2 ----------------
__global__ void coef_kernel(const float* __restrict__ C, const float* __restrict__ c) {
    int tb = blockIdx.x;
    int tid = threadIdx.x;   // 96 threads, 3 warps
    __shared__ float sz[SZ_], sd[SZ_];
    __shared__ float sw0[3], sw1[3], sw2[3];

    sz[tid] = g_z0[(size_t)tb * SZ_ + tid];
    sd[tid] = g_dz[(size_t)tb * SZ_ + tid];
    __syncthreads();

    const float* col = C + (size_t)tb * SZ_ * SZ_ + tid;
    float y0 = 0.f, yd = 0.f;
#pragma unroll 8
    for (int j = 0; j < SZ_; j++) {
        float cij = col[j * SZ_];
        y0 += cij * sz[j];
        yd += cij * sd[j];
    }
    float cv = c[(size_t)tb * SZ_ + tid];
    float p0 = sz[tid] * (0.5f * y0 + cv);
    float p1 = sd[tid] * (y0 + cv);
    float p2 = 0.5f * sd[tid] * yd;

#pragma unroll
    for (int o = 16; o > 0; o >>= 1) {
        p0 += __shfl_down_sync(0xffffffffu, p0, o);
        p1 += __shfl_down_sync(0xffffffffu, p1, o);
        p2 += __shfl_down_sync(0xffffffffu, p2, o);
    }
    if ((tid & 31) == 0) { int w = tid >> 5; sw0[w] = p0; sw1[w] = p1; sw2[w] = p2; }
    __syncthreads();
    if (tid == 0) {
        g_q0[tb] = sw0[0] + sw0[1] + sw0[2];
        g_q1[tb] = sw1[0] + sw1[1] + sw1[2];
        g_q2[tb] = sw2[0] + sw2[1] + sw2[2];
    }
}

// ---------------- fused line-search resolve + outputs (one block per batch) ----------------
__global__ void finish_kernel(float* __restrict__ out) {
    int b = blockIdx.x;       // 512 blocks
    int tid = threadIdx.x;    // 256
    __shared__ float s_alpha;

    if (tid < 32) {
        int idx = tid * B_ + b;     // t = tid (T_ == 32)
        float old = g_costpart[idx];
        float A0 = g_q0[idx], A1 = g_q1[idx], A2 = g_q2[idx];
#pragma unroll
        for (int o = 16; o > 0; o >>= 1) {
            old += __shfl_down_sync(0xffffffffu, old, o);
            A0  += __shfl_down_sync(0xffffffffu, A0,  o);
            A1  += __shfl_down_sync(0xffffffffu, A1,  o);
            A2  += __shfl_down_sync(0xffffffffu, A2,  o);
        }
        if (tid == 0) {
            float alpha = 1.f;
#pragma unroll
            for (int i = 0; i < 3; i++) {
                float cst = A0 + alpha * (A1 + alpha * A2);
                if (cst > old) alpha *= 0.5f;
            }
            float cur = A0 + alpha * (A1 + alpha * A2);
            out[(size_t)T_ * B_ * (NS_ + NC_) + b] = cur;
            s_alpha = alpha;
        }
    }
    __syncthreads();
    float alpha = s_alpha;

    for (int idx = tid; idx < T_ * SZ_; idx += 256) {
        int t = idx / SZ_, s = idx % SZ_;
        size_t tb = (size_t)t * B_ + b;
        size_t g = tb * SZ_ + s;
        float val = g_z0[g] + alpha * g_dz[g];
        if (s < NS_) out[tb * NS_ + s] = val;
        else         out[(size_t)T_ * B_ * NS_ + tb * NC_ + (s - NS_)] = val;
    }
}

// ---------------- launch ----------------
extern "C" void kernel_launch(void* const* d_in, const int* in_sizes, int n_in,
                              void* d_out, int out_size) {
    const float *x = nullptr, *u = nullptr, *xi = nullptr, *C = nullptr, *c = nullptr, *F = nullptr;
    for (int i = 0; i < n_in; i++) {
        long long s = in_sizes[i];
        const float* p = (const float*)d_in[i];
        if      (s == (long long)T_ * B_ * SZ_ * SZ_) C = p;
        else if (s == (long long)T_ * B_ * NS_ * SZ_) F = p;
        else if (s == (long long)T_ * B_ * SZ_)       c = p;
        else if (s == (long long)T_ * B_ * NS_)       x = p;
        else if (s == (long long)T_ * B_ * NC_)       u = p;
        else if (s == (long long)B_ * NS_)            xi = p;
    }
    float* out = (float*)d_out;

    cudaFuncSetAttribute(backward_kernel, cudaFuncAttributeMaxDynamicSharedMemorySize, BK_SMEM);

    prep_kernel<<<T_ * B_, 96>>>(x, u, C, c);
    backward_kernel<<<B_, 256, BK_SMEM>>>(C, F);
    rollout_kernel<<<B_, 128>>>(x, u, xi, F);
    coef_kernel<<<T_ * B_, 96>>>(C, c);
    finish_kernel<<<B_, 256>>>(out);
}